// round 14
// baseline (speedup 1.0000x reference)
#include <cuda_runtime.h>
#include <cuda_fp16.h>
#include <cstdint>

#define HW   196
#define NC   128
#define NB   8
#define CIN  512
#define NPIX 256
#define MM   16384
#define EPSV 1e-11f
#define KPAD 208            // K padded to 13 k-steps of 16
#define XDW  424            // doubled-row width (halfs)
#define XRS  232            // Xr smem row stride (halfs)
#define TGW  1664           // g_xdT global row stride (halfs)
#define TSS  872            // T smem row stride (halfs)
#define WSZ  802816         // 4096*196 = 49*16384

// ---------------- device scratch (.bss zero-init) --------------------------
__device__ float  g_yp  [4][NB * NC * NPIX];
__device__ __half g_xrh [NB * NC * KPAD];
__device__ __half g_xdh [NB * NC * XDW];     // raw[j]   = X[j mod 196]
__device__ __half g_xdh1[NB * NC * XDW];     // raw1[j]  = X[(j+1) mod 196]
__device__ __half g_xdT [(size_t)NB * NC * TGW];  // interleaved frag stream
__device__ float  g_W   [(size_t)NB * WSZ];
__device__ float  g_Q   [NB * 7 * 16384];
__device__ float  g_part[NB * 64];
__device__ float  g_norm[NB];

// ---------------- Kernel A: partial y = W @ x (K-split by 4) ---------------
__global__ void __launch_bounds__(256) pw4(const float* __restrict__ x,
                                           const float* __restrict__ w) {
    __shared__ float xs[32][64];
    __shared__ float ws[32][32];
    int bz = blockIdx.z, b = bz >> 2, ks = bz & 3;
    int o0 = blockIdx.y * 32, px0 = blockIdx.x * 64;
    int tid = threadIdx.x, px = tid & 63, og = tid >> 6;
    float acc[8];
#pragma unroll
    for (int u = 0; u < 8; u++) acc[u] = 0.f;
    const float* xb = x + b * CIN * NPIX;
    int ibase = ks * 128;
    for (int i0 = ibase; i0 < ibase + 128; i0 += 32) {
        __syncthreads();
#pragma unroll
        for (int r = 0; r < 8; r++) {
            int idx = tid + r * 256;
            xs[idx >> 6][idx & 63] = xb[(i0 + (idx >> 6)) * NPIX + px0 + (idx & 63)];
        }
#pragma unroll
        for (int r = 0; r < 4; r++) {
            int idx = tid + r * 256;
            ws[idx >> 5][idx & 31] = w[(o0 + (idx >> 5)) * CIN + i0 + (idx & 31)];
        }
        __syncthreads();
#pragma unroll
        for (int i = 0; i < 32; i++) {
            float xv = xs[i][px];
#pragma unroll
            for (int u = 0; u < 8; u++)
                acc[u] = fmaf(ws[og * 8 + u][i], xv, acc[u]);
        }
    }
    float* yb = g_yp[ks] + b * NC * NPIX;
#pragma unroll
    for (int u = 0; u < 8; u++)
        yb[(o0 + og * 8 + u) * NPIX + px0 + px] = acc[u];
}

// ---------------- Kernel B: sum + relu + gaussian + fp16 prep ---------------
__global__ void __launch_bounds__(256) prep() {
    __shared__ float s[256];
    int b = blockIdx.y, c = blockIdx.x, t = threadIdx.x;
    int off = (b * NC + c) * NPIX + t;
    s[t] = fmaxf(g_yp[0][off] + g_yp[1][off] + g_yp[2][off] + g_yp[3][off], 0.f);
    __syncthreads();
    if (t < HW) {
        const float G0 = 0.63661977f, G1 = 0.08615711f, G2 = 0.01166010f;
        int oy = t / 14, ox = t - oy * 14;
        int r0 = oy * 16 + ox, r1 = r0 + 16, r2 = r0 + 32;
        float v = G2 * (s[r0] + s[r0 + 2] + s[r2] + s[r2 + 2])
                + G1 * (s[r0 + 1] + s[r1] + s[r1 + 2] + s[r2 + 1])
                + G0 * s[r1 + 1];
        __half h = __float2half_rn(v);
        g_xrh[(b * NC + c) * KPAD + (195 - t)] = h;
        __half* xd = g_xdh + (size_t)(b * NC + c) * XDW;
        xd[t]      = h;
        xd[t + HW] = h;
        if (t < 32) xd[t + 392] = h;
        __half* x1 = g_xdh1 + (size_t)(b * NC + c) * XDW;
        x1[t + 195] = h;
        if (t) x1[t - 1] = h;
        if (t < 33) x1[t + 391] = h;
    }
}

// ---------------- Kernel B2: build interleaved fragment stream T -----------
// T[8t+4q+e] = raw_q[2t + (e&1) + (e&2)*4], raw_q = raw shifted by q
__global__ void __launch_bounds__(256) prep2() {
    int b = blockIdx.y, c = blockIdx.x, tid = threadIdx.x;
    size_t row = (size_t)(b * NC + c);
    const __half* x0 = g_xdh  + row * XDW;
    const __half* x1 = g_xdh1 + row * XDW;
    __half* T = g_xdT + row * TGW;
    for (int j = tid; j < 1632; j += 256) {
        int t = j >> 3, q = (j >> 2) & 1, e = j & 3;
        int idx = 2 * t + (e & 1) + ((e & 2) << 2);
        T[j] = q ? x1[idx] : x0[idx];
    }
}

__device__ __forceinline__ uint32_t smem_u32(const void* p) {
    uint32_t a;
    asm("{ .reg .u64 t; cvta.to.shared.u64 t, %1; cvt.u32.u64 %0, t; }"
        : "=r"(a) : "l"(p));
    return a;
}

// ---------------- Kernel C: fp16 mma corr, LDS.64 B-fragments --------------
// CTA: M=128 x N=128 (16 c x 8 p), K=208. 16 warps = 4 wm x 4 wn, tile 32x32.
__global__ void __launch_bounds__(512, 2) corr12() {
    extern __shared__ char dyn[];
    __half* XrS = (__half*)dyn;                      // [128][XRS] 59392B
    __half* XdT = (__half*)(dyn + 128 * XRS * 2);    // [16][TSS]  27904B
    float*  sbuf = (float*)dyn;                      // epilogue overlay 48KB

    int b  = blockIdx.z;
    int c0 = blockIdx.y * 16;
    int p0 = blockIdx.x * 8;
    int tid = threadIdx.x;

    // stage Xr: 128 rows x 26 int4
    {
        const int4* xr = (const int4*)(g_xrh + (size_t)b * NC * KPAD);
        for (int i = tid; i < 3328; i += 512) {
            int r = i / 26, q = i - r * 26;
            *(int4*)(XrS + r * XRS + q * 8) = xr[r * 26 + q];
        }
    }
    // stage T windows: 16 rows x 108 int4 (864 halfs from half-offset 4*p0)
    for (int i = tid; i < 1728; i += 512) {
        int r = i / 108, o = i - r * 108;
        const int4* src = (const int4*)(g_xdT + (size_t)(b * NC + c0 + r) * TGW
                                        + 4 * p0);
        *(int4*)(XdT + r * TSS + o * 8) = src[o];
    }
    __syncthreads();

    int lane = tid & 31, w = tid >> 5;
    int wm = w >> 2, wn = w & 3;
    int lr = lane >> 2, lk = lane & 3;

    // A addresses: warp wm covers a = wm*32 + mi*16 + frag rows
    uint32_t a_addr[2];
    {
        int arow = wm * 32 + (lane & 7) + ((lane >> 3) & 1) * 8;
        int acol = (lane >> 4) * 8;
        uint32_t base = smem_u32(XrS);
#pragma unroll
        for (int mi = 0; mi < 2; mi++)
            a_addr[mi] = base + (uint32_t)(((arow + mi * 16) * XRS + acol) * 2);
    }

    // B pointers: lane (n=lr, lk): q=(n+1)&1, tb=lk+((n+1)>>1)
    const __half* bptr[4];
    {
        int n = lr;
        const __half* base = XdT + 8 * (lk + ((n + 1) >> 1)) + 4 * ((n + 1) & 1);
#pragma unroll
        for (int nt = 0; nt < 4; nt++)
            bptr[nt] = base + (wn * 4 + nt) * TSS;
    }

    float acc[2][4][4];
#pragma unroll
    for (int mi = 0; mi < 2; mi++)
#pragma unroll
        for (int nt = 0; nt < 4; nt++)
#pragma unroll
            for (int u = 0; u < 4; u++) acc[mi][nt][u] = 0.f;

#pragma unroll
    for (int k = 0; k < KPAD; k += 16) {
        uint32_t af[2][4];
#pragma unroll
        for (int mi = 0; mi < 2; mi++) {
            asm volatile(
                "ldmatrix.sync.aligned.m8n8.x4.shared.b16 {%0,%1,%2,%3}, [%4];"
                : "=r"(af[mi][0]), "=r"(af[mi][1]),
                  "=r"(af[mi][2]), "=r"(af[mi][3])
                : "r"(a_addr[mi] + (uint32_t)(k * 2)));
        }
#pragma unroll
        for (int nt = 0; nt < 4; nt++) {
            uint2 bb = *(const uint2*)(bptr[nt] + 4 * k);   // b0 | b1 in one LDS.64
#pragma unroll
            for (int mi = 0; mi < 2; mi++) {
                asm volatile(
                    "mma.sync.aligned.m16n8k16.row.col.f32.f16.f16.f32 "
                    "{%0,%1,%2,%3},{%4,%5,%6,%7},{%8,%9},{%0,%1,%2,%3};"
                    : "+f"(acc[mi][nt][0]), "+f"(acc[mi][nt][1]),
                      "+f"(acc[mi][nt][2]), "+f"(acc[mi][nt][3])
                    : "r"(af[mi][0]), "r"(af[mi][1]),
                      "r"(af[mi][2]), "r"(af[mi][3]),
                      "r"(bb.x), "r"(bb.y));
            }
        }
    }

    // cross-warp fold over wm (a-group g = mi*16 + fragrow, same for all wm)
    __syncthreads();   // operands consumed; overlay sbuf
    if (wm != 0) {
        float* dst = sbuf + ((wm - 1) * 4 + wn) * 1024 + lane;
#pragma unroll
        for (int mi = 0; mi < 2; mi++)
#pragma unroll
            for (int nt = 0; nt < 4; nt++)
#pragma unroll
                for (int u = 0; u < 4; u++)
                    dst[((mi * 4 + nt) * 4 + u) * 32] = acc[mi][nt][u];
    }
    __syncthreads();
    if (wm == 0) {
        int pe = p0 + lk * 2;
        float* Wb = g_W + (size_t)b * WSZ;
        const float* s1 = sbuf + (0 * 4 + wn) * 1024 + lane;
        const float* s2 = sbuf + (1 * 4 + wn) * 1024 + lane;
        const float* s3 = sbuf + (2 * 4 + wn) * 1024 + lane;
#pragma unroll
        for (int mi = 0; mi < 2; mi++)
#pragma unroll
            for (int nt = 0; nt < 4; nt++) {
                float v[4];
#pragma unroll
                for (int u = 0; u < 4; u++) {
                    int sl = ((mi * 4 + nt) * 4 + u) * 32;
                    v[u] = fmaxf(fmaxf(acc[mi][nt][u], s1[sl]),
                                 fmaxf(s2[sl], s3[sl]));
                }
                if (pe < HW) {
                    int c  = c0 + wn * 4 + nt;
                    int s0 = (mi * 16 + lr) * 128 + c;
                    *(float2*)(Wb + (size_t)s0 * HW + pe) = make_float2(v[0], v[1]);
                    *(float2*)(Wb + (size_t)(s0 + 8 * 128) * HW + pe) =
                        make_float2(v[2], v[3]);
                }
            }
    }
}

// ---------------- Kernel D1: partial max over 7 j's (2 cols/thread) --------
__global__ void __launch_bounds__(256) maxredA() {
    int b = blockIdx.z, jc = blockIdx.y;
    int m4 = blockIdx.x * 256 + threadIdx.x;
    const float4* Wb = (const float4*)(g_W + (size_t)b * WSZ);
    float4 a0 = make_float4(0.f, 0.f, 0.f, 0.f), a1 = a0;
#pragma unroll
    for (int u = 0; u < 7; u++) {
        float4 v0 = Wb[(size_t)(jc * 7 + u) * 4096 + m4];
        float4 v1 = Wb[(size_t)(jc * 7 + u) * 4096 + m4 + 2048];
        a0.x = fmaxf(a0.x, v0.x); a0.y = fmaxf(a0.y, v0.y);
        a0.z = fmaxf(a0.z, v0.z); a0.w = fmaxf(a0.w, v0.w);
        a1.x = fmaxf(a1.x, v1.x); a1.y = fmaxf(a1.y, v1.y);
        a1.z = fmaxf(a1.z, v1.z); a1.w = fmaxf(a1.w, v1.w);
    }
    ((float4*)g_Q)[(b * 7 + jc) * 4096 + m4] = a0;
    ((float4*)g_Q)[(b * 7 + jc) * 4096 + m4 + 2048] = a1;
}

// ---------------- Kernel D2: combine + sqrt + norm partials ----------------
__global__ void __launch_bounds__(256) maxredB(float* __restrict__ out) {
    int b = blockIdx.y;
    int m4 = blockIdx.x * 256 + threadIdx.x;
    float4 a = make_float4(0.f, 0.f, 0.f, 0.f);
#pragma unroll
    for (int jc = 0; jc < 7; jc++) {
        float4 v = ((const float4*)g_Q)[(b * 7 + jc) * 4096 + m4];
        a.x = fmaxf(a.x, v.x); a.y = fmaxf(a.y, v.y);
        a.z = fmaxf(a.z, v.z); a.w = fmaxf(a.w, v.w);
    }
    float4 r = make_float4(sqrtf(a.x), sqrtf(a.y), sqrtf(a.z), sqrtf(a.w));
    ((float4*)(out + b * MM))[m4] = r;

    float v = r.x * r.x + r.y * r.y + r.z * r.z + r.w * r.w;
#pragma unroll
    for (int off = 16; off; off >>= 1) v += __shfl_down_sync(0xffffffffu, v, off);
    __shared__ float ssum[8];
    if ((threadIdx.x & 31) == 0) ssum[threadIdx.x >> 5] = v;
    __syncthreads();
    if (threadIdx.x == 0) {
        float s = 0.f;
#pragma unroll
        for (int i = 0; i < 8; i++) s += ssum[i];
        g_part[b * 64 + blockIdx.x] = s;   // blocks 0..15; 16..63 stay 0 (.bss)
    }
}

__global__ void normk() {
    __shared__ float s[64];
    int b = blockIdx.x, t = threadIdx.x;
    s[t] = g_part[b * 64 + t];
    __syncthreads();
#pragma unroll
    for (int st = 32; st; st >>= 1) {
        if (t < st) s[t] += s[t + st];
        __syncthreads();
    }
    if (t == 0) g_norm[b] = s[0] + EPSV;
}

__global__ void __launch_bounds__(256) divk(float* __restrict__ out) {
    int i = blockIdx.x * 256 + threadIdx.x;
    out[i] = out[i] / g_norm[i >> 14];
}

// ---------------- launch ----------------------------------------------------
extern "C" void kernel_launch(void* const* d_in, const int* in_sizes, int n_in,
                              void* d_out, int out_size) {
    const float* x = (const float*)d_in[0];
    const float* w = (const float*)d_in[1];
    if (in_sizes[0] == NC * CIN) { const float* t = x; x = w; w = t; }
    float* out = (float*)d_out;

    pw4<<<dim3(4, 4, NB * 4), 256>>>(x, w);       // launch 1
    prep<<<dim3(NC, NB), 256>>>();                // launch 2
    prep2<<<dim3(NC, NB), 256>>>();               // launch 3
    // launch 4 -> ncu capture slot
    int smem = 128 * XRS * 2 + 16 * TSS * 2;      // 87296 bytes
    cudaFuncSetAttribute(corr12, cudaFuncAttributeMaxDynamicSharedMemorySize, smem);
    corr12<<<dim3(25, 8, NB), 512, smem>>>();

    maxredA<<<dim3(8, 7, NB), 256>>>();
    maxredB<<<dim3(16, NB), 256>>>(out);
    normk<<<NB, 64>>>();
    divk<<<512, 256>>>(out);
}

// round 15
// speedup vs baseline: 1.0817x; 1.0817x over previous
#include <cuda_runtime.h>
#include <cuda_fp16.h>
#include <cstdint>

#define HW   196
#define NC   128
#define NB   8
#define CIN  512
#define NPIX 256
#define MM   16384
#define EPSV 1e-11f
#define KPAD 208            // K padded to 13 k-steps of 16
#define XDW  424            // doubled-row width (halfs)
#define XRS  232            // Xr smem row stride (halfs)
#define XDS  224            // Xd smem row width (halfs)
#define WSZ  802816         // 4096*196 = 49*16384

// ---------------- device scratch (.bss zero-init) --------------------------
__device__ float  g_yp  [4][NB * NC * NPIX];
__device__ __half g_xrh [NB * NC * KPAD];
__device__ __half g_xdh [NB * NC * XDW];     // xd[j] = X[j mod 196]
__device__ __half g_xdh1[NB * NC * XDW];     // x1[j] = X[(j+1) mod 196]
__device__ float  g_W   [(size_t)NB * WSZ];  // [b][f], f=(a32*128+c)*196+p
__device__ float  g_Q   [NB * 7 * 16384];
__device__ float  g_part[NB * 64];

// ---------------- Kernel A: partial y = W @ x (K-split by 4) ---------------
__global__ void __launch_bounds__(256) pw4(const float* __restrict__ x,
                                           const float* __restrict__ w) {
    __shared__ float xs[32][64];
    __shared__ float ws[32][32];
    int bz = blockIdx.z, b = bz >> 2, ks = bz & 3;
    int o0 = blockIdx.y * 32, px0 = blockIdx.x * 64;
    int tid = threadIdx.x, px = tid & 63, og = tid >> 6;
    float acc[8];
#pragma unroll
    for (int u = 0; u < 8; u++) acc[u] = 0.f;
    const float* xb = x + b * CIN * NPIX;
    int ibase = ks * 128;
    for (int i0 = ibase; i0 < ibase + 128; i0 += 32) {
        __syncthreads();
#pragma unroll
        for (int r = 0; r < 8; r++) {
            int idx = tid + r * 256;
            xs[idx >> 6][idx & 63] = xb[(i0 + (idx >> 6)) * NPIX + px0 + (idx & 63)];
        }
#pragma unroll
        for (int r = 0; r < 4; r++) {
            int idx = tid + r * 256;
            ws[idx >> 5][idx & 31] = w[(o0 + (idx >> 5)) * CIN + i0 + (idx & 31)];
        }
        __syncthreads();
#pragma unroll
        for (int i = 0; i < 32; i++) {
            float xv = xs[i][px];
#pragma unroll
            for (int u = 0; u < 8; u++)
                acc[u] = fmaf(ws[og * 8 + u][i], xv, acc[u]);
        }
    }
    float* yb = g_yp[ks] + b * NC * NPIX;
#pragma unroll
    for (int u = 0; u < 8; u++)
        yb[(o0 + og * 8 + u) * NPIX + px0 + px] = acc[u];
}

// ---------------- Kernel B: sum + relu + gaussian + fp16 prep ---------------
__global__ void __launch_bounds__(256) prep() {
    __shared__ float s[256];
    int b = blockIdx.y, c = blockIdx.x, t = threadIdx.x;
    int off = (b * NC + c) * NPIX + t;
    s[t] = fmaxf(g_yp[0][off] + g_yp[1][off] + g_yp[2][off] + g_yp[3][off], 0.f);
    __syncthreads();
    if (t < HW) {
        const float G0 = 0.63661977f, G1 = 0.08615711f, G2 = 0.01166010f;
        int oy = t / 14, ox = t - oy * 14;
        int r0 = oy * 16 + ox, r1 = r0 + 16, r2 = r0 + 32;
        float v = G2 * (s[r0] + s[r0 + 2] + s[r2] + s[r2 + 2])
                + G1 * (s[r0 + 1] + s[r1] + s[r1 + 2] + s[r2 + 1])
                + G0 * s[r1 + 1];
        __half h = __float2half_rn(v);
        g_xrh[(b * NC + c) * KPAD + (195 - t)] = h;
        __half* xd = g_xdh + (size_t)(b * NC + c) * XDW;
        xd[t]      = h;
        xd[t + HW] = h;
        if (t < 32) xd[t + 392] = h;
        __half* x1 = g_xdh1 + (size_t)(b * NC + c) * XDW;
        x1[t + 195] = h;
        if (t) x1[t - 1] = h;
        if (t < 33) x1[t + 391] = h;
    }
}

// ---------------- shim: keeps corr in ncu slot 4 (zeros unused g_part) -----
__global__ void zerok() {
    int i = blockIdx.x * 256 + threadIdx.x;
    if (i < NB * 64) g_part[i] = (i & 63) < 16 ? g_part[i] : 0.f;
}

__device__ __forceinline__ uint32_t smem_u32(const void* p) {
    uint32_t a;
    asm("{ .reg .u64 t; cvta.to.shared.u64 t, %1; cvt.u32.u64 %0, t; }"
        : "=r"(a) : "l"(p));
    return a;
}

// ---------------- Kernel C: fp16 mma corr, A-fragment ping-pong ------------
// CTA: M=128 x N=128 (16 c x 8 p), K=208. 16 warps = 4 wm x 4 wn, tile 32x32.
__global__ void __launch_bounds__(512, 2) corr13() {
    extern __shared__ char dyn[];
    __half* XrS = (__half*)dyn;                         // [128][XRS] 59392B
    __half* XdA = (__half*)(dyn + 128 * XRS * 2);       // [16][XDS]
    __half* XdB = XdA + 16 * XDS + 16;                  // [16][XDS], bank shift
    float*  sbuf = (float*)dyn;                         // epilogue overlay 48KB

    int b  = blockIdx.z;
    int c0 = blockIdx.y * 16;
    int p0 = blockIdx.x * 8;
    int tid = threadIdx.x;

    // stage Xr: 128 rows x 26 int4
    {
        const int4* xr = (const int4*)(g_xrh + (size_t)b * NC * KPAD);
        for (int i = tid; i < 3328; i += 512) {
            int r = i / 26, q = i - r * 26;
            *(int4*)(XrS + r * XRS + q * 8) = xr[r * 26 + q];
        }
    }
    // stage XdA (window, unshifted) and XdB (window, +1 shifted)
    for (int i = tid; i < 896; i += 512) {
        int sel = (i >= 448);
        int ii = sel ? (i - 448) : i;
        int r = ii / 28, q = ii - r * 28;
        const __half* src = (sel ? g_xdh1 : g_xdh)
                          + (size_t)(b * NC + c0 + r) * XDW + p0 + q * 8;
        __half* dst = (sel ? XdB : XdA) + r * XDS + q * 8;
        *(int4*)dst = *(const int4*)src;
    }
    __syncthreads();

    int lane = tid & 31, w = tid >> 5;
    int wm = w >> 2, wn = w & 3;
    int lr = lane >> 2, lk = lane & 3;

    uint32_t a_addr[2];
    {
        int arow = wm * 32 + (lane & 7) + ((lane >> 3) & 1) * 8;
        int acol = (lane >> 4) * 8;
        uint32_t base = smem_u32(XrS);
#pragma unroll
        for (int mi = 0; mi < 2; mi++)
            a_addr[mi] = base + (uint32_t)(((arow + mi * 32) * XRS + acol) * 2);
        // NOTE: mi stride 32 rows? No -- warp tile is 32m = 2 x 16m tiles.
        a_addr[1] = base + (uint32_t)(((arow + 16) * XRS + acol) * 2);
        a_addr[0] = base + (uint32_t)((arow * XRS + acol) * 2);
    }

    const __half* brow[4];
    {
        const __half* pb = (lr & 1) ? (XdA + lr + 1) : (XdB + lr);
#pragma unroll
        for (int nt = 0; nt < 4; nt++)
            brow[nt] = pb + (wn * 4 + nt) * XDS + lk * 2;
    }

    float acc[2][4][4];
#pragma unroll
    for (int mi = 0; mi < 2; mi++)
#pragma unroll
        for (int nt = 0; nt < 4; nt++)
#pragma unroll
            for (int u = 0; u < 4; u++) acc[mi][nt][u] = 0.f;

    uint32_t afA[2][4], afB[2][4];
    // prologue: load k=0 fragments into afA
#pragma unroll
    for (int mi = 0; mi < 2; mi++) {
        asm volatile(
            "ldmatrix.sync.aligned.m8n8.x4.shared.b16 {%0,%1,%2,%3}, [%4];"
            : "=r"(afA[mi][0]), "=r"(afA[mi][1]),
              "=r"(afA[mi][2]), "=r"(afA[mi][3])
            : "r"(a_addr[mi]));
    }

#pragma unroll
    for (int ks = 0; ks < 13; ks++) {
        // prefetch next k-step's A fragments into the alternate buffer
        if (ks < 12) {
            uint32_t koff = (uint32_t)((ks + 1) * 32);   // bytes
            if (ks & 1) {
#pragma unroll
                for (int mi = 0; mi < 2; mi++)
                    asm volatile(
                        "ldmatrix.sync.aligned.m8n8.x4.shared.b16 {%0,%1,%2,%3}, [%4];"
                        : "=r"(afA[mi][0]), "=r"(afA[mi][1]),
                          "=r"(afA[mi][2]), "=r"(afA[mi][3])
                        : "r"(a_addr[mi] + koff));
            } else {
#pragma unroll
                for (int mi = 0; mi < 2; mi++)
                    asm volatile(
                        "ldmatrix.sync.aligned.m8n8.x4.shared.b16 {%0,%1,%2,%3}, [%4];"
                        : "=r"(afB[mi][0]), "=r"(afB[mi][1]),
                          "=r"(afB[mi][2]), "=r"(afB[mi][3])
                        : "r"(a_addr[mi] + koff));
            }
        }
        int k = ks * 16;
#pragma unroll
        for (int nt = 0; nt < 4; nt++) {
            uint32_t b0 = *(const uint32_t*)(brow[nt] + k);
            uint32_t b1 = *(const uint32_t*)(brow[nt] + k + 8);
#pragma unroll
            for (int mi = 0; mi < 2; mi++) {
                if (ks & 1) {
                    asm volatile(
                        "mma.sync.aligned.m16n8k16.row.col.f32.f16.f16.f32 "
                        "{%0,%1,%2,%3},{%4,%5,%6,%7},{%8,%9},{%0,%1,%2,%3};"
                        : "+f"(acc[mi][nt][0]), "+f"(acc[mi][nt][1]),
                          "+f"(acc[mi][nt][2]), "+f"(acc[mi][nt][3])
                        : "r"(afB[mi][0]), "r"(afB[mi][1]),
                          "r"(afB[mi][2]), "r"(afB[mi][3]),
                          "r"(b0), "r"(b1));
                } else {
                    asm volatile(
                        "mma.sync.aligned.m16n8k16.row.col.f32.f16.f16.f32 "
                        "{%0,%1,%2,%3},{%4,%5,%6,%7},{%8,%9},{%0,%1,%2,%3};"
                        : "+f"(acc[mi][nt][0]), "+f"(acc[mi][nt][1]),
                          "+f"(acc[mi][nt][2]), "+f"(acc[mi][nt][3])
                        : "r"(afA[mi][0]), "r"(afA[mi][1]),
                          "r"(afA[mi][2]), "r"(afA[mi][3]),
                          "r"(b0), "r"(b1));
                }
            }
        }
    }

    // cross-warp fold over wm
    __syncthreads();
    if (wm != 0) {
        float* dst = sbuf + ((wm - 1) * 4 + wn) * 1024 + lane;
#pragma unroll
        for (int mi = 0; mi < 2; mi++)
#pragma unroll
            for (int nt = 0; nt < 4; nt++)
#pragma unroll
                for (int u = 0; u < 4; u++)
                    dst[((mi * 4 + nt) * 4 + u) * 32] = acc[mi][nt][u];
    }
    __syncthreads();
    if (wm == 0) {
        int pe = p0 + lk * 2;
        float* Wb = g_W + (size_t)b * WSZ;
        const float* s1 = sbuf + (0 * 4 + wn) * 1024 + lane;
        const float* s2 = sbuf + (1 * 4 + wn) * 1024 + lane;
        const float* s3 = sbuf + (2 * 4 + wn) * 1024 + lane;
#pragma unroll
        for (int mi = 0; mi < 2; mi++)
#pragma unroll
            for (int nt = 0; nt < 4; nt++) {
                float v[4];
#pragma unroll
                for (int u = 0; u < 4; u++) {
                    int sl = ((mi * 4 + nt) * 4 + u) * 32;
                    v[u] = fmaxf(fmaxf(acc[mi][nt][u], s1[sl]),
                                 fmaxf(s2[sl], s3[sl]));
                }
                if (pe < HW) {
                    int c  = c0 + wn * 4 + nt;
                    int s0 = (mi * 16 + lr) * 128 + c;
                    *(float2*)(Wb + (size_t)s0 * HW + pe) = make_float2(v[0], v[1]);
                    *(float2*)(Wb + (size_t)(s0 + 8 * 128) * HW + pe) =
                        make_float2(v[2], v[3]);
                }
            }
    }
}

// ---------------- Kernel D1: partial max over 7 j's (2 cols/thread) --------
__global__ void __launch_bounds__(256) maxredA() {
    int b = blockIdx.z, jc = blockIdx.y;
    int m4 = blockIdx.x * 256 + threadIdx.x;
    const float4* Wb = (const float4*)(g_W + (size_t)b * WSZ);
    float4 a0 = make_float4(0.f, 0.f, 0.f, 0.f), a1 = a0;
#pragma unroll
    for (int u = 0; u < 7; u++) {
        float4 v0 = Wb[(size_t)(jc * 7 + u) * 4096 + m4];
        float4 v1 = Wb[(size_t)(jc * 7 + u) * 4096 + m4 + 2048];
        a0.x = fmaxf(a0.x, v0.x); a0.y = fmaxf(a0.y, v0.y);
        a0.z = fmaxf(a0.z, v0.z); a0.w = fmaxf(a0.w, v0.w);
        a1.x = fmaxf(a1.x, v1.x); a1.y = fmaxf(a1.y, v1.y);
        a1.z = fmaxf(a1.z, v1.z); a1.w = fmaxf(a1.w, v1.w);
    }
    ((float4*)g_Q)[(b * 7 + jc) * 4096 + m4] = a0;
    ((float4*)g_Q)[(b * 7 + jc) * 4096 + m4 + 2048] = a1;
}

// ---------------- Kernel D2: combine + sqrt + norm partials ----------------
__global__ void __launch_bounds__(256) maxredB(float* __restrict__ out) {
    int b = blockIdx.y;
    int m4 = blockIdx.x * 256 + threadIdx.x;
    float4 a = make_float4(0.f, 0.f, 0.f, 0.f);
#pragma unroll
    for (int jc = 0; jc < 7; jc++) {
        float4 v = ((const float4*)g_Q)[(b * 7 + jc) * 4096 + m4];
        a.x = fmaxf(a.x, v.x); a.y = fmaxf(a.y, v.y);
        a.z = fmaxf(a.z, v.z); a.w = fmaxf(a.w, v.w);
    }
    float4 r = make_float4(sqrtf(a.x), sqrtf(a.y), sqrtf(a.z), sqrtf(a.w));
    ((float4*)(out + b * MM))[m4] = r;

    float v = r.x * r.x + r.y * r.y + r.z * r.z + r.w * r.w;
#pragma unroll
    for (int off = 16; off; off >>= 1) v += __shfl_down_sync(0xffffffffu, v, off);
    __shared__ float ssum[8];
    if ((threadIdx.x & 31) == 0) ssum[threadIdx.x >> 5] = v;
    __syncthreads();
    if (threadIdx.x == 0) {
        float s = 0.f;
#pragma unroll
        for (int i = 0; i < 8; i++) s += ssum[i];
        g_part[b * 64 + blockIdx.x] = s;
    }
}

// ---------------- Kernel E: fused norm-sum + divide -------------------------
__global__ void __launch_bounds__(256) divnorm(float* __restrict__ out) {
    int i = blockIdx.x * 256 + threadIdx.x;
    int b = i >> 14;
    __shared__ float nrm;
    if (threadIdx.x < 16) {
        float v = g_part[b * 64 + threadIdx.x];
#pragma unroll
        for (int off = 8; off; off >>= 1)
            v += __shfl_down_sync(0xffffu, v, off);
        if (threadIdx.x == 0) nrm = v + EPSV;
    }
    __syncthreads();
    out[i] = out[i] / nrm;
}

// ---------------- launch ----------------------------------------------------
extern "C" void kernel_launch(void* const* d_in, const int* in_sizes, int n_in,
                              void* d_out, int out_size) {
    const float* x = (const float*)d_in[0];
    const float* w = (const float*)d_in[1];
    if (in_sizes[0] == NC * CIN) { const float* t = x; x = w; w = t; }
    float* out = (float*)d_out;

    pw4<<<dim3(4, 4, NB * 4), 256>>>(x, w);       // launch 1
    prep<<<dim3(NC, NB), 256>>>();                // launch 2
    zerok<<<2, 256>>>();                          // launch 3 (shim)

    int smem = (128 * XRS + 2 * 16 * XDS + 16) * 2;   // 73760 bytes
    cudaFuncSetAttribute(corr13, cudaFuncAttributeMaxDynamicSharedMemorySize, smem);
    corr13<<<dim3(25, 8, NB), 512, smem>>>();     // launch 4 -> ncu capture

    maxredA<<<dim3(8, 7, NB), 256>>>();
    maxredB<<<dim3(16, NB), 256>>>(out);
    divnorm<<<512, 256>>>(out);
}

// round 16
// speedup vs baseline: 1.1987x; 1.1082x over previous
#include <cuda_runtime.h>
#include <cuda_fp16.h>
#include <cstdint>

#define HW   196
#define NC   128
#define NB   8
#define CIN  512
#define NPIX 256
#define MM   16384
#define EPSV 1e-11f
#define KPAD 208            // K padded to 13 k-steps of 16
#define XDW  424            // doubled-row width (halfs)
#define XRS  232            // Xr smem row stride (halfs)
#define XDS2 432            // Xd smem full-row stride (halfs, 16B-mult)
#define WSZ  802816         // 4096*196 = 49*16384

// ---------------- device scratch (.bss zero-init) --------------------------
__device__ float  g_yp  [4][NB * NC * NPIX];
__device__ __half g_xrh [NB * NC * KPAD];
__device__ __half g_xdh [NB * NC * XDW];     // xd[j] = X[j mod 196]
__device__ __half g_xdh1[NB * NC * XDW];     // x1[j] = X[(j+1) mod 196]
__device__ float  g_W   [(size_t)NB * WSZ];  // [b][f], f=(a32*128+c)*196+p
__device__ float  g_part[NB * 64];

// ---------------- Kernel A: partial y = W @ x (K-split by 4) ---------------
__global__ void __launch_bounds__(256) pw4(const float* __restrict__ x,
                                           const float* __restrict__ w) {
    __shared__ float xs[32][64];
    __shared__ float ws[32][32];
    int bz = blockIdx.z, b = bz >> 2, ks = bz & 3;
    int o0 = blockIdx.y * 32, px0 = blockIdx.x * 64;
    int tid = threadIdx.x, px = tid & 63, og = tid >> 6;
    float acc[8];
#pragma unroll
    for (int u = 0; u < 8; u++) acc[u] = 0.f;
    const float* xb = x + b * CIN * NPIX;
    int ibase = ks * 128;
    for (int i0 = ibase; i0 < ibase + 128; i0 += 32) {
        __syncthreads();
#pragma unroll
        for (int r = 0; r < 8; r++) {
            int idx = tid + r * 256;
            xs[idx >> 6][idx & 63] = xb[(i0 + (idx >> 6)) * NPIX + px0 + (idx & 63)];
        }
#pragma unroll
        for (int r = 0; r < 4; r++) {
            int idx = tid + r * 256;
            ws[idx >> 5][idx & 31] = w[(o0 + (idx >> 5)) * CIN + i0 + (idx & 31)];
        }
        __syncthreads();
#pragma unroll
        for (int i = 0; i < 32; i++) {
            float xv = xs[i][px];
#pragma unroll
            for (int u = 0; u < 8; u++)
                acc[u] = fmaf(ws[og * 8 + u][i], xv, acc[u]);
        }
    }
    float* yb = g_yp[ks] + b * NC * NPIX;
#pragma unroll
    for (int u = 0; u < 8; u++)
        yb[(o0 + og * 8 + u) * NPIX + px0 + px] = acc[u];
}

// ---------------- Kernel B: sum + relu + gaussian + fp16 prep ---------------
__global__ void __launch_bounds__(256) prep() {
    __shared__ float s[256];
    int b = blockIdx.y, c = blockIdx.x, t = threadIdx.x;
    int off = (b * NC + c) * NPIX + t;
    s[t] = fmaxf(g_yp[0][off] + g_yp[1][off] + g_yp[2][off] + g_yp[3][off], 0.f);
    __syncthreads();
    if (t < HW) {
        const float G0 = 0.63661977f, G1 = 0.08615711f, G2 = 0.01166010f;
        int oy = t / 14, ox = t - oy * 14;
        int r0 = oy * 16 + ox, r1 = r0 + 16, r2 = r0 + 32;
        float v = G2 * (s[r0] + s[r0 + 2] + s[r2] + s[r2 + 2])
                + G1 * (s[r0 + 1] + s[r1] + s[r1 + 2] + s[r2 + 1])
                + G0 * s[r1 + 1];
        __half h = __float2half_rn(v);
        g_xrh[(b * NC + c) * KPAD + (195 - t)] = h;
        __half* xd = g_xdh + (size_t)(b * NC + c) * XDW;
        xd[t]      = h;
        xd[t + HW] = h;
        if (t < 32) xd[t + 392] = h;
        __half* x1 = g_xdh1 + (size_t)(b * NC + c) * XDW;
        x1[t + 195] = h;
        if (t) x1[t - 1] = h;
        if (t < 33) x1[t + 391] = h;
    }
}

// ---------------- shim: zero g_part; keeps corr in ncu slot 4 --------------
__global__ void zerok() {
    int i = blockIdx.x * 256 + threadIdx.x;
    if (i < NB * 64) g_part[i] = 0.f;
}

__device__ __forceinline__ uint32_t smem_u32(const void* p) {
    uint32_t a;
    asm("{ .reg .u64 t; cvta.to.shared.u64 t, %1; cvt.u32.u64 %0, t; }"
        : "=r"(a) : "l"(p));
    return a;
}

// ---------------- Kernel C: persistent p-loop, register-only 4-fold --------
// CTA: M=128 x N=128 (16c x 8p), K=208; 16 warps (4wm x 4wn), tile 32m x 32n.
// Xr staged with PERMUTED rows: smem row r holds a = (r&7) + 32*((r>>3)&3)
// + 8*(r>>5)  ->  warp wm's fragment rows are exactly the 4 aliases of
// groups g in [8wm, 8wm+8): fold is 6 fmax in registers, no smem exchange.
// Grid (9 ptg, 8 ct, 8 b); each CTA loops 2-3 p-tiles reusing staged data.
__global__ void __launch_bounds__(512, 2) corrP() {
    extern __shared__ char dyn[];
    __half* XrS = (__half*)dyn;                      // [128][XRS]   59392B
    __half* XdA = (__half*)(dyn + 59392);            // [16][XDS2]   13824B
    __half* XdB = (__half*)(dyn + 73248);            // +32B pad, bank shift

    int b = blockIdx.z, c0 = blockIdx.y * 16, ptg = blockIdx.x;
    int tid = threadIdx.x;

    // stage Xr (permuted rows): 128 rows x 26 int4
    {
        const int4* xr = (const int4*)(g_xrh + (size_t)b * NC * KPAD);
        for (int i = tid; i < 3328; i += 512) {
            int r = i / 26, q = i - r * 26;
            int a = (r & 7) + ((r >> 3) & 3) * 32 + (r >> 5) * 8;
            *(int4*)(XrS + r * XRS + q * 8) = xr[a * 26 + q];
        }
    }
    // stage full Xd rows, both parities: 16 rows x 53 int4 each
    for (int i = tid; i < 1696; i += 512) {
        int sel = (i >= 848);
        int ii = sel ? (i - 848) : i;
        int r = ii / 53, q = ii - r * 53;
        const __half* src = (sel ? g_xdh1 : g_xdh)
                          + (size_t)(b * NC + c0 + r) * XDW + q * 8;
        __half* dst = (sel ? XdB : XdA) + r * XDS2 + q * 8;
        *(int4*)dst = *(const int4*)src;
    }
    __syncthreads();

    int lane = tid & 31, w = tid >> 5;
    int wm = w >> 2, wn = w & 3;
    int lr = lane >> 2, lk = lane & 3;

    uint32_t a_addr[2];
    {
        int arow = wm * 32 + (lane & 7) + ((lane >> 3) & 1) * 8;
        int acol = (lane >> 4) * 8;
        uint32_t base = smem_u32(XrS);
        a_addr[0] = base + (uint32_t)((arow * XRS + acol) * 2);
        a_addr[1] = base + (uint32_t)(((arow + 16) * XRS + acol) * 2);
    }
    const __half* brow[4];
    {
        const __half* pb = (lr & 1) ? (XdA + lr + 1) : (XdB + lr);
#pragma unroll
        for (int nt = 0; nt < 4; nt++)
            brow[nt] = pb + (wn * 4 + nt) * XDS2 + lk * 2;
    }
    float* Wb = g_W + (size_t)b * WSZ;
    int g = wm * 8 + lr;

    int npt = (ptg < 7) ? 3 : 2;
    int pt0 = (ptg < 7) ? ptg * 3 : 21 + (ptg - 7) * 2;

    for (int ip = 0; ip < npt; ip++) {
        int p0 = (pt0 + ip) * 8;
        float acc[2][4][4];
#pragma unroll
        for (int mi = 0; mi < 2; mi++)
#pragma unroll
            for (int nt = 0; nt < 4; nt++)
#pragma unroll
                for (int u = 0; u < 4; u++) acc[mi][nt][u] = 0.f;

#pragma unroll
        for (int ks = 0; ks < 13; ks++) {
            int k = ks * 16;
            uint32_t af[2][4];
#pragma unroll
            for (int mi = 0; mi < 2; mi++) {
                asm volatile(
                    "ldmatrix.sync.aligned.m8n8.x4.shared.b16 {%0,%1,%2,%3}, [%4];"
                    : "=r"(af[mi][0]), "=r"(af[mi][1]),
                      "=r"(af[mi][2]), "=r"(af[mi][3])
                    : "r"(a_addr[mi] + (uint32_t)(k * 2)));
            }
            int off = k + p0;
#pragma unroll
            for (int nt = 0; nt < 4; nt++) {
                uint32_t b0 = *(const uint32_t*)(brow[nt] + off);
                uint32_t b1 = *(const uint32_t*)(brow[nt] + off + 8);
#pragma unroll
                for (int mi = 0; mi < 2; mi++) {
                    asm volatile(
                        "mma.sync.aligned.m16n8k16.row.col.f32.f16.f16.f32 "
                        "{%0,%1,%2,%3},{%4,%5,%6,%7},{%8,%9},{%0,%1,%2,%3};"
                        : "+f"(acc[mi][nt][0]), "+f"(acc[mi][nt][1]),
                          "+f"(acc[mi][nt][2]), "+f"(acc[mi][nt][3])
                        : "r"(af[mi][0]), "r"(af[mi][1]),
                          "r"(af[mi][2]), "r"(af[mi][3]),
                          "r"(b0), "r"(b1));
                }
            }
        }

        // register-only 4-alias fold + direct W write
        int pe = p0 + lk * 2;
        if (pe < HW) {
#pragma unroll
            for (int nt = 0; nt < 4; nt++) {
                float v0 = fmaxf(fmaxf(acc[0][nt][0], acc[0][nt][2]),
                                 fmaxf(acc[1][nt][0], acc[1][nt][2]));
                float v1 = fmaxf(fmaxf(acc[0][nt][1], acc[0][nt][3]),
                                 fmaxf(acc[1][nt][1], acc[1][nt][3]));
                int c = c0 + wn * 4 + nt;
                *(float2*)(Wb + (size_t)(g * NC + c) * HW + pe) =
                    make_float2(v0, v1);
            }
        }
    }
}

// ---------------- Kernel D: fused max over 49 rows + sqrt + norm -----------
__global__ void __launch_bounds__(256) maxredC(float* __restrict__ out) {
    int b = blockIdx.y;
    int m4 = blockIdx.x * 256 + threadIdx.x;   // 0..4095
    const float4* Wb = (const float4*)(g_W + (size_t)b * WSZ);
    float4 a = make_float4(0.f, 0.f, 0.f, 0.f);
#pragma unroll 7
    for (int j = 0; j < 49; j++) {
        float4 v = Wb[(size_t)j * 4096 + m4];
        a.x = fmaxf(a.x, v.x); a.y = fmaxf(a.y, v.y);
        a.z = fmaxf(a.z, v.z); a.w = fmaxf(a.w, v.w);
    }
    float4 r = make_float4(sqrtf(a.x), sqrtf(a.y), sqrtf(a.z), sqrtf(a.w));
    ((float4*)(out + b * MM))[m4] = r;

    float v = r.x * r.x + r.y * r.y + r.z * r.z + r.w * r.w;
#pragma unroll
    for (int off = 16; off; off >>= 1) v += __shfl_down_sync(0xffffffffu, v, off);
    __shared__ float ssum[8];
    if ((threadIdx.x & 31) == 0) ssum[threadIdx.x >> 5] = v;
    __syncthreads();
    if (threadIdx.x == 0) {
        float s = 0.f;
#pragma unroll
        for (int i = 0; i < 8; i++) s += ssum[i];
        g_part[b * 64 + blockIdx.x] = s;   // blockIdx.x < 16
    }
}

// ---------------- Kernel E: fused norm-sum + divide -------------------------
__global__ void __launch_bounds__(256) divnorm(float* __restrict__ out) {
    int i = blockIdx.x * 256 + threadIdx.x;
    int b = i >> 14;
    __shared__ float nrm;
    if (threadIdx.x < 16) {
        float v = g_part[b * 64 + threadIdx.x];
#pragma unroll
        for (int off = 8; off; off >>= 1)
            v += __shfl_down_sync(0xffffu, v, off);
        if (threadIdx.x == 0) nrm = v + EPSV;
    }
    __syncthreads();
    out[i] = out[i] / nrm;
}

// ---------------- launch ----------------------------------------------------
extern "C" void kernel_launch(void* const* d_in, const int* in_sizes, int n_in,
                              void* d_out, int out_size) {
    const float* x = (const float*)d_in[0];
    const float* w = (const float*)d_in[1];
    if (in_sizes[0] == NC * CIN) { const float* t = x; x = w; w = t; }
    float* out = (float*)d_out;

    pw4<<<dim3(4, 4, NB * 4), 256>>>(x, w);       // launch 1
    prep<<<dim3(NC, NB), 256>>>();                // launch 2
    zerok<<<2, 256>>>();                          // launch 3 (shim)

    int smem = 73248 + 16 * XDS2 * 2;             // 87072 bytes
    cudaFuncSetAttribute(corrP, cudaFuncAttributeMaxDynamicSharedMemorySize, smem);
    corrP<<<dim3(9, 8, NB), 512, smem>>>();       // launch 4 -> ncu capture

    maxredC<<<dim3(16, NB), 256>>>(out);
    divnorm<<<512, 256>>>(out);
}

// round 17
// speedup vs baseline: 1.4018x; 1.1694x over previous
#include <cuda_runtime.h>
#include <cuda_fp16.h>
#include <cstdint>

#define HW   196
#define NC   128
#define NB   8
#define CIN  512
#define NPIX 256
#define MM   16384
#define EPSV 1e-11f
#define KPAD 208            // K padded to 13 k-steps of 16
#define XDW  424            // doubled-row width (halfs)
#define XRS  232            // Xr smem row stride (halfs)
#define XDS2 432            // Xd smem full-row stride (halfs, 16B-mult)
#define WSZ  802816         // 4096*196 = 49*16384
#define AS_S 68             // pwtc As row stride (floats)
#define BS_S 68             // pwtc Bs row stride (floats)

// ---------------- device scratch (.bss zero-init) --------------------------
__device__ float  g_yp  [4][NB * NC * NPIX];
__device__ __half g_xrh [NB * NC * KPAD];
__device__ __half g_xdh [NB * NC * XDW];     // xd[j] = X[j mod 196]
__device__ __half g_xdh1[NB * NC * XDW];     // x1[j] = X[(j+1) mod 196]
__device__ float  g_W   [(size_t)NB * WSZ];  // [b][f], f=(a32*128+c)*196+p
__device__ float  g_part[NB * 64];

__device__ __forceinline__ float to_tf32(float f) {
    uint32_t u;
    asm("cvt.rna.tf32.f32 %0, %1;" : "=r"(u) : "f"(f));
    return __uint_as_float(u);
}

// ---------------- Kernel A: tf32 tensor pointwise conv (K-split by 4) ------
// CTA: 128 o x 64 px, K-chunk 128. 8 warps = 4 wm(o) x 2 wn(px), tile 32x32.
__global__ void __launch_bounds__(256) pwtc(const float* __restrict__ x,
                                            const float* __restrict__ w) {
    extern __shared__ float sm[];
    float* As = sm;                    // [128][AS_S]
    float* Bs = sm + 128 * AS_S;       // [64][BS_S]

    int b = blockIdx.z, ks = blockIdx.y, px0 = blockIdx.x * 64;
    int K0 = ks * 128;
    int tid = threadIdx.x;
    int lane = tid & 31, w5 = tid >> 5;
    int wm = w5 >> 1, wn = w5 & 1;
    int lr = lane >> 2, lk = lane & 3;

    float acc[2][4][4];
#pragma unroll
    for (int mi = 0; mi < 2; mi++)
#pragma unroll
        for (int nt = 0; nt < 4; nt++)
#pragma unroll
            for (int u = 0; u < 4; u++) acc[mi][nt][u] = 0.f;

    const float* xb = x + (size_t)b * CIN * NPIX;

    for (int kc = 0; kc < 128; kc += 64) {
        __syncthreads();
        // stage As: 128 rows x 16 float4 (w rows, tf32-rounded)
        for (int i = tid; i < 2048; i += 256) {
            int r = i >> 4, q = i & 15;
            float4 v = *(const float4*)(w + r * CIN + K0 + kc + q * 4);
            v.x = to_tf32(v.x); v.y = to_tf32(v.y);
            v.z = to_tf32(v.z); v.w = to_tf32(v.w);
            *(float4*)(As + r * AS_S + q * 4) = v;
        }
        // stage Bs: 64 rows x 16 float4 (x rows, tf32-rounded)
        for (int i = tid; i < 1024; i += 256) {
            int r = i >> 4, q = i & 15;
            float4 v = *(const float4*)(xb + (K0 + kc + r) * NPIX + px0 + q * 4);
            v.x = to_tf32(v.x); v.y = to_tf32(v.y);
            v.z = to_tf32(v.z); v.w = to_tf32(v.w);
            *(float4*)(Bs + r * BS_S + q * 4) = v;
        }
        __syncthreads();

#pragma unroll
        for (int k8 = 0; k8 < 64; k8 += 8) {
            uint32_t af[2][4];
#pragma unroll
            for (int mi = 0; mi < 2; mi++) {
                const float* ap = As + (wm * 32 + mi * 16 + lr) * AS_S + k8 + lk;
                af[mi][0] = __float_as_uint(ap[0]);
                af[mi][1] = __float_as_uint(ap[8 * AS_S]);
                af[mi][2] = __float_as_uint(ap[4]);
                af[mi][3] = __float_as_uint(ap[8 * AS_S + 4]);
            }
#pragma unroll
            for (int nt = 0; nt < 4; nt++) {
                const float* bp = Bs + (k8 + lk) * BS_S + wn * 32 + nt * 8 + lr;
                uint32_t b0 = __float_as_uint(bp[0]);
                uint32_t b1 = __float_as_uint(bp[4 * BS_S]);
#pragma unroll
                for (int mi = 0; mi < 2; mi++) {
                    asm volatile(
                        "mma.sync.aligned.m16n8k8.row.col.f32.tf32.tf32.f32 "
                        "{%0,%1,%2,%3},{%4,%5,%6,%7},{%8,%9},{%0,%1,%2,%3};"
                        : "+f"(acc[mi][nt][0]), "+f"(acc[mi][nt][1]),
                          "+f"(acc[mi][nt][2]), "+f"(acc[mi][nt][3])
                        : "r"(af[mi][0]), "r"(af[mi][1]),
                          "r"(af[mi][2]), "r"(af[mi][3]),
                          "r"(b0), "r"(b1));
                }
            }
        }
    }

    float* yb = g_yp[ks] + b * NC * NPIX;
#pragma unroll
    for (int mi = 0; mi < 2; mi++) {
        int o = wm * 32 + mi * 16 + lr;
#pragma unroll
        for (int nt = 0; nt < 4; nt++) {
            int px = px0 + wn * 32 + nt * 8 + lk * 2;
            *(float2*)(yb + o * NPIX + px) =
                make_float2(acc[mi][nt][0], acc[mi][nt][1]);
            *(float2*)(yb + (o + 8) * NPIX + px) =
                make_float2(acc[mi][nt][2], acc[mi][nt][3]);
        }
    }
}

// ---------------- Kernel B: sum + relu + gaussian + fp16 prep ---------------
__global__ void __launch_bounds__(256) prep() {
    __shared__ float s[256];
    int b = blockIdx.y, c = blockIdx.x, t = threadIdx.x;
    int off = (b * NC + c) * NPIX + t;
    s[t] = fmaxf(g_yp[0][off] + g_yp[1][off] + g_yp[2][off] + g_yp[3][off], 0.f);
    __syncthreads();
    if (t < HW) {
        const float G0 = 0.63661977f, G1 = 0.08615711f, G2 = 0.01166010f;
        int oy = t / 14, ox = t - oy * 14;
        int r0 = oy * 16 + ox, r1 = r0 + 16, r2 = r0 + 32;
        float v = G2 * (s[r0] + s[r0 + 2] + s[r2] + s[r2 + 2])
                + G1 * (s[r0 + 1] + s[r1] + s[r1 + 2] + s[r2 + 1])
                + G0 * s[r1 + 1];
        __half h = __float2half_rn(v);
        g_xrh[(b * NC + c) * KPAD + (195 - t)] = h;
        __half* xd = g_xdh + (size_t)(b * NC + c) * XDW;
        xd[t]      = h;
        xd[t + HW] = h;
        if (t < 32) xd[t + 392] = h;
        __half* x1 = g_xdh1 + (size_t)(b * NC + c) * XDW;
        x1[t + 195] = h;
        if (t) x1[t - 1] = h;
        if (t < 33) x1[t + 391] = h;
    }
}

// ---------------- shim: zero g_part; keeps corr in ncu slot 4 --------------
__global__ void zerok() {
    int i = blockIdx.x * 256 + threadIdx.x;
    if (i < NB * 64) g_part[i] = 0.f;
}

__device__ __forceinline__ uint32_t smem_u32(const void* p) {
    uint32_t a;
    asm("{ .reg .u64 t; cvta.to.shared.u64 t, %1; cvt.u32.u64 %0, t; }"
        : "=r"(a) : "l"(p));
    return a;
}

// ---------------- Kernel C: persistent p-loop, register-only 4-fold --------
__global__ void __launch_bounds__(512, 2) corrP() {
    extern __shared__ char dyn[];
    __half* XrS = (__half*)dyn;                      // [128][XRS]   59392B
    __half* XdA = (__half*)(dyn + 59392);            // [16][XDS2]   13824B
    __half* XdB = (__half*)(dyn + 73248);            // +32B pad, bank shift

    int b = blockIdx.z, c0 = blockIdx.y * 16, ptg = blockIdx.x;
    int tid = threadIdx.x;

    {
        const int4* xr = (const int4*)(g_xrh + (size_t)b * NC * KPAD);
        for (int i = tid; i < 3328; i += 512) {
            int r = i / 26, q = i - r * 26;
            int a = (r & 7) + ((r >> 3) & 3) * 32 + (r >> 5) * 8;
            *(int4*)(XrS + r * XRS + q * 8) = xr[a * 26 + q];
        }
    }
    for (int i = tid; i < 1696; i += 512) {
        int sel = (i >= 848);
        int ii = sel ? (i - 848) : i;
        int r = ii / 53, q = ii - r * 53;
        const __half* src = (sel ? g_xdh1 : g_xdh)
                          + (size_t)(b * NC + c0 + r) * XDW + q * 8;
        __half* dst = (sel ? XdB : XdA) + r * XDS2 + q * 8;
        *(int4*)dst = *(const int4*)src;
    }
    __syncthreads();

    int lane = tid & 31, w = tid >> 5;
    int wm = w >> 2, wn = w & 3;
    int lr = lane >> 2, lk = lane & 3;

    uint32_t a_addr[2];
    {
        int arow = wm * 32 + (lane & 7) + ((lane >> 3) & 1) * 8;
        int acol = (lane >> 4) * 8;
        uint32_t base = smem_u32(XrS);
        a_addr[0] = base + (uint32_t)((arow * XRS + acol) * 2);
        a_addr[1] = base + (uint32_t)(((arow + 16) * XRS + acol) * 2);
    }
    const __half* brow[4];
    {
        const __half* pb = (lr & 1) ? (XdA + lr + 1) : (XdB + lr);
#pragma unroll
        for (int nt = 0; nt < 4; nt++)
            brow[nt] = pb + (wn * 4 + nt) * XDS2 + lk * 2;
    }
    float* Wb = g_W + (size_t)b * WSZ;
    int g = wm * 8 + lr;

    int npt = (ptg < 7) ? 3 : 2;
    int pt0 = (ptg < 7) ? ptg * 3 : 21 + (ptg - 7) * 2;

    for (int ip = 0; ip < npt; ip++) {
        int p0 = (pt0 + ip) * 8;
        float acc[2][4][4];
#pragma unroll
        for (int mi = 0; mi < 2; mi++)
#pragma unroll
            for (int nt = 0; nt < 4; nt++)
#pragma unroll
                for (int u = 0; u < 4; u++) acc[mi][nt][u] = 0.f;

#pragma unroll
        for (int ks = 0; ks < 13; ks++) {
            int k = ks * 16;
            uint32_t af[2][4];
#pragma unroll
            for (int mi = 0; mi < 2; mi++) {
                asm volatile(
                    "ldmatrix.sync.aligned.m8n8.x4.shared.b16 {%0,%1,%2,%3}, [%4];"
                    : "=r"(af[mi][0]), "=r"(af[mi][1]),
                      "=r"(af[mi][2]), "=r"(af[mi][3])
                    : "r"(a_addr[mi] + (uint32_t)(k * 2)));
            }
            int off = k + p0;
#pragma unroll
            for (int nt = 0; nt < 4; nt++) {
                uint32_t b0 = *(const uint32_t*)(brow[nt] + off);
                uint32_t b1 = *(const uint32_t*)(brow[nt] + off + 8);
#pragma unroll
                for (int mi = 0; mi < 2; mi++) {
                    asm volatile(
                        "mma.sync.aligned.m16n8k16.row.col.f32.f16.f16.f32 "
                        "{%0,%1,%2,%3},{%4,%5,%6,%7},{%8,%9},{%0,%1,%2,%3};"
                        : "+f"(acc[mi][nt][0]), "+f"(acc[mi][nt][1]),
                          "+f"(acc[mi][nt][2]), "+f"(acc[mi][nt][3])
                        : "r"(af[mi][0]), "r"(af[mi][1]),
                          "r"(af[mi][2]), "r"(af[mi][3]),
                          "r"(b0), "r"(b1));
                }
            }
        }

        int pe = p0 + lk * 2;
        if (pe < HW) {
#pragma unroll
            for (int nt = 0; nt < 4; nt++) {
                float v0 = fmaxf(fmaxf(acc[0][nt][0], acc[0][nt][2]),
                                 fmaxf(acc[1][nt][0], acc[1][nt][2]));
                float v1 = fmaxf(fmaxf(acc[0][nt][1], acc[0][nt][3]),
                                 fmaxf(acc[1][nt][1], acc[1][nt][3]));
                int c = c0 + wn * 4 + nt;
                *(float2*)(Wb + (size_t)(g * NC + c) * HW + pe) =
                    make_float2(v0, v1);
            }
        }
    }
}

// ---------------- Kernel D: fused max over 49 rows + sqrt + norm -----------
__global__ void __launch_bounds__(256) maxredC(float* __restrict__ out) {
    int b = blockIdx.y;
    int m4 = blockIdx.x * 256 + threadIdx.x;
    const float4* Wb = (const float4*)(g_W + (size_t)b * WSZ);
    float4 a = make_float4(0.f, 0.f, 0.f, 0.f);
#pragma unroll 7
    for (int j = 0; j < 49; j++) {
        float4 v = Wb[(size_t)j * 4096 + m4];
        a.x = fmaxf(a.x, v.x); a.y = fmaxf(a.y, v.y);
        a.z = fmaxf(a.z, v.z); a.w = fmaxf(a.w, v.w);
    }
    float4 r = make_float4(sqrtf(a.x), sqrtf(a.y), sqrtf(a.z), sqrtf(a.w));
    ((float4*)(out + b * MM))[m4] = r;

    float v = r.x * r.x + r.y * r.y + r.z * r.z + r.w * r.w;
#pragma unroll
    for (int off = 16; off; off >>= 1) v += __shfl_down_sync(0xffffffffu, v, off);
    __shared__ float ssum[8];
    if ((threadIdx.x & 31) == 0) ssum[threadIdx.x >> 5] = v;
    __syncthreads();
    if (threadIdx.x == 0) {
        float s = 0.f;
#pragma unroll
        for (int i = 0; i < 8; i++) s += ssum[i];
        g_part[b * 64 + blockIdx.x] = s;
    }
}

// ---------------- Kernel E: fused norm-sum + divide -------------------------
__global__ void __launch_bounds__(256) divnorm(float* __restrict__ out) {
    int i = blockIdx.x * 256 + threadIdx.x;
    int b = i >> 14;
    __shared__ float nrm;
    if (threadIdx.x < 16) {
        float v = g_part[b * 64 + threadIdx.x];
#pragma unroll
        for (int off = 8; off; off >>= 1)
            v += __shfl_down_sync(0xffffu, v, off);
        if (threadIdx.x == 0) nrm = v + EPSV;
    }
    __syncthreads();
    out[i] = out[i] / nrm;
}

// ---------------- launch ----------------------------------------------------
extern "C" void kernel_launch(void* const* d_in, const int* in_sizes, int n_in,
                              void* d_out, int out_size) {
    const float* x = (const float*)d_in[0];
    const float* w = (const float*)d_in[1];
    if (in_sizes[0] == NC * CIN) { const float* t = x; x = w; w = t; }
    float* out = (float*)d_out;

    int psmem = (128 * AS_S + 64 * BS_S) * 4;     // 52224 bytes
    cudaFuncSetAttribute(pwtc, cudaFuncAttributeMaxDynamicSharedMemorySize, psmem);
    pwtc<<<dim3(4, 4, NB), 256, psmem>>>(x, w);   // launch 1

    prep<<<dim3(NC, NB), 256>>>();                // launch 2
    zerok<<<2, 256>>>();                          // launch 3 (shim)

    int smem = 73248 + 16 * XDS2 * 2;             // 87072 bytes
    cudaFuncSetAttribute(corrP, cudaFuncAttributeMaxDynamicSharedMemorySize, smem);
    corrP<<<dim3(9, 8, NB), 512, smem>>>();       // launch 4 -> ncu capture

    maxredC<<<dim3(16, NB), 256>>>(out);
    divnorm<<<512, 256>>>(out);
}